// round 15
// baseline (speedup 1.0000x reference)
#include <cuda_runtime.h>
#include <cuda_fp16.h>
#include <math.h>
#include <stdint.h>

#define NMAX 50000
#define EMAX 800000
#define TOT_E (EMAX + NMAX)

// ---------------- scratch ----------------
__device__ __half g_xph[NMAX * 256];
__device__ float  g_asrc[NMAX * 8];
__device__ float  g_adst[NMAX * 8];
__device__ int    g_deg[NMAX];
__device__ int    g_rowstart[NMAX + 1];
__device__ int    g_cursor[NMAX];
__device__ int    g_csr[TOT_E];
__device__ float  g_hp[NMAX * 2];
__device__ float  g_as2[NMAX];
__device__ float  g_ad2[NMAX];
__device__ int    g_is64;
__device__ int    g_bsum[256];

// ---------------- mma helpers ----------------
__device__ __forceinline__ uint32_t sptr(const void* p) {
    return (uint32_t)__cvta_generic_to_shared(p);
}
__device__ __forceinline__ void ldsm4(uint32_t* r, uint32_t a) {
    asm volatile("ldmatrix.sync.aligned.m8n8.x4.shared.b16 {%0,%1,%2,%3},[%4];"
        : "=r"(r[0]), "=r"(r[1]), "=r"(r[2]), "=r"(r[3]) : "r"(a));
}
__device__ __forceinline__ void ldsm4t(uint32_t* r, uint32_t a) {
    asm volatile("ldmatrix.sync.aligned.m8n8.x4.trans.shared.b16 {%0,%1,%2,%3},[%4];"
        : "=r"(r[0]), "=r"(r[1]), "=r"(r[2]), "=r"(r[3]) : "r"(a));
}
__device__ __forceinline__ void mma16816(float* c, const uint32_t* a, uint32_t b0, uint32_t b1) {
    asm volatile(
        "mma.sync.aligned.m16n8k16.row.col.f32.f16.f16.f32 "
        "{%0,%1,%2,%3},{%4,%5,%6,%7},{%8,%9},{%0,%1,%2,%3};"
        : "+f"(c[0]), "+f"(c[1]), "+f"(c[2]), "+f"(c[3])
        : "r"(a[0]), "r"(a[1]), "r"(a[2]), "r"(a[3]), "r"(b0), "r"(b1));
}

__device__ __forceinline__ int load_idx(const void* ei, int i, int is64) {
    if (is64) return (int)((const long long*)ei)[i];
    return ((const int*)ei)[i];
}

// ---------------- init: zero deg + parallel dtype detect ----------------
__global__ void k_init(const int* __restrict__ ei32, int n) {
    int t = blockIdx.x * blockDim.x + threadIdx.x;
    if (t < n) g_deg[t] = 0;
    if (blockIdx.x == 0 && threadIdx.x < 32) {
        int bad = 0;
        #pragma unroll
        for (int i = threadIdx.x; i < 64; i += 32)
            bad |= (ei32[2 * i + 1] != 0);
        unsigned m = __ballot_sync(0xffffffffu, bad);
        if (threadIdx.x == 0) g_is64 = (m == 0);
    }
}

// ---------------- layer-1 GEMM + fused attention logits (double-buffered) ----------------
__global__ void __launch_bounds__(256, 2) k_gemm1(const float* __restrict__ X,
                                                  const float* __restrict__ W,
                                                  const float* __restrict__ As1,
                                                  const float* __restrict__ Ad1, int M) {
    const int BM = 128;
    __shared__ __half As[2][BM][40];
    __shared__ __half Bs[2][32][136];
    __shared__ float  sA[128][4];
    __shared__ float  sD[128][4];
    int t    = threadIdx.x;
    int wid  = t >> 5, lane = t & 31;
    int lr   = lane & 7, lg = lane >> 3;
    int wm   = (wid >> 1) * 32;
    int wn   = (wid & 1) * 64;
    int rowBase = blockIdx.x * BM;
    int colBase = blockIdx.y * BM;
    int hb      = blockIdx.y * 4;

    #pragma unroll
    for (int i = t; i < 512; i += 256) {
        ((float*)sA)[i] = 0.f;
        ((float*)sD)[i] = 0.f;
    }

    float c[2][8][4];
    #pragma unroll
    for (int i = 0; i < 2; i++)
        #pragma unroll
        for (int j = 0; j < 8; j++)
            #pragma unroll
            for (int k = 0; k < 4; k++) c[i][j][k] = 0.f;

    int ar[4], ak[4], br[4], bc[4];
    #pragma unroll
    for (int i = 0; i < 4; i++) {
        int q = t + i * 256;
        ar[i] = q >> 3; ak[i] = (q & 7) * 4;
        br[i] = q >> 5; bc[i] = (q & 31) * 4;
    }

    float4 ra[4], rb[4];
    #pragma unroll
    for (int i = 0; i < 4; i++) {
        int grow = rowBase + ar[i];
        ra[i] = (grow < M) ? *(const float4*)(X + (size_t)grow * 256 + ak[i])
                           : make_float4(0.f, 0.f, 0.f, 0.f);
        rb[i] = *(const float4*)(W + (size_t)br[i] * 256 + colBase + bc[i]);
    }
    #pragma unroll
    for (int i = 0; i < 4; i++) {
        *(__half2*)&As[0][ar[i]][ak[i]]     = __floats2half2_rn(ra[i].x, ra[i].y);
        *(__half2*)&As[0][ar[i]][ak[i] + 2] = __floats2half2_rn(ra[i].z, ra[i].w);
        *(__half2*)&Bs[0][br[i]][bc[i]]     = __floats2half2_rn(rb[i].x, rb[i].y);
        *(__half2*)&Bs[0][br[i]][bc[i] + 2] = __floats2half2_rn(rb[i].z, rb[i].w);
    }
    __syncthreads();

    int cur = 0;
    for (int kt = 0; kt < 256; kt += 32) {
        bool more = (kt + 32) < 256;
        if (more) {
            #pragma unroll
            for (int i = 0; i < 4; i++) {
                int grow = rowBase + ar[i];
                ra[i] = (grow < M) ? *(const float4*)(X + (size_t)grow * 256 + kt + 32 + ak[i])
                                   : make_float4(0.f, 0.f, 0.f, 0.f);
                rb[i] = *(const float4*)(W + (size_t)(kt + 32 + br[i]) * 256 + colBase + bc[i]);
            }
        }
        #pragma unroll
        for (int ks = 0; ks < 2; ks++) {
            uint32_t a[2][4], b[4][4];
            #pragma unroll
            for (int mt = 0; mt < 2; mt++) {
                int row = wm + mt * 16 + lr + (lg & 1) * 8;
                int col = ks * 16 + (lg >> 1) * 8;
                ldsm4(a[mt], sptr(&As[cur][row][col]));
            }
            #pragma unroll
            for (int ng = 0; ng < 4; ng++) {
                int krow = ks * 16 + lr + (lg & 1) * 8;
                int col  = wn + ng * 16 + (lg >> 1) * 8;
                ldsm4t(b[ng], sptr(&Bs[cur][krow][col]));
            }
            #pragma unroll
            for (int mt = 0; mt < 2; mt++)
                #pragma unroll
                for (int nt = 0; nt < 8; nt++)
                    mma16816(c[mt][nt], a[mt], b[nt >> 1][(nt & 1) * 2],
                             b[nt >> 1][(nt & 1) * 2 + 1]);
        }
        if (more) {
            int nxt = cur ^ 1;
            #pragma unroll
            for (int i = 0; i < 4; i++) {
                *(__half2*)&As[nxt][ar[i]][ak[i]]     = __floats2half2_rn(ra[i].x, ra[i].y);
                *(__half2*)&As[nxt][ar[i]][ak[i] + 2] = __floats2half2_rn(ra[i].z, ra[i].w);
                *(__half2*)&Bs[nxt][br[i]][bc[i]]     = __floats2half2_rn(rb[i].x, rb[i].y);
                *(__half2*)&Bs[nxt][br[i]][bc[i] + 2] = __floats2half2_rn(rb[i].z, rb[i].w);
            }
            __syncthreads();
            cur = nxt;
        }
    }

    // epilogue 1: store xp fp16
    #pragma unroll
    for (int mt = 0; mt < 2; mt++) {
        int r0 = rowBase + wm + mt * 16 + (lane >> 2);
        #pragma unroll
        for (int nt = 0; nt < 8; nt++) {
            int col = colBase + wn + nt * 8 + (lane & 3) * 2;
            if (r0 < M)
                *(__half2*)(g_xph + (size_t)r0 * 256 + col) =
                    __floats2half2_rn(c[mt][nt][0], c[mt][nt][1]);
            if (r0 + 8 < M)
                *(__half2*)(g_xph + (size_t)(r0 + 8) * 256 + col) =
                    __floats2half2_rn(c[mt][nt][2], c[mt][nt][3]);
        }
    }

    // epilogue 2: attention logit partials
    float asw[16], adw[16];
    #pragma unroll
    for (int nt = 0; nt < 8; nt++)
        #pragma unroll
        for (int b = 0; b < 2; b++) {
            int col = wn + nt * 8 + (lane & 3) * 2 + b;
            asw[nt * 2 + b] = As1[colBase + col];
            adw[nt * 2 + b] = Ad1[colBase + col];
        }
    int h0 = wn >> 5, h1 = h0 + 1;
    #pragma unroll
    for (int mt = 0; mt < 2; mt++)
        #pragma unroll
        for (int hf = 0; hf < 2; hf++) {
            int rl = wm + mt * 16 + (lane >> 2) + 8 * hf;
            float s0 = 0.f, s1 = 0.f, d0 = 0.f, d1 = 0.f;
            #pragma unroll
            for (int nt = 0; nt < 8; nt++) {
                float v0 = c[mt][nt][hf * 2 + 0];
                float v1 = c[mt][nt][hf * 2 + 1];
                float cs = v0 * asw[nt * 2] + v1 * asw[nt * 2 + 1];
                float cd = v0 * adw[nt * 2] + v1 * adw[nt * 2 + 1];
                if (nt < 4) { s0 += cs; d0 += cd; }
                else        { s1 += cs; d1 += cd; }
            }
            atomicAdd(&sA[rl][h0], s0);
            atomicAdd(&sA[rl][h1], s1);
            atomicAdd(&sD[rl][h0], d0);
            atomicAdd(&sD[rl][h1], d1);
        }
    __syncthreads();
    #pragma unroll
    for (int i = t; i < 512; i += 256) {
        int r = i >> 2, hl = i & 3;
        int grow = rowBase + r;
        if (grow < M) {
            g_asrc[grow * 8 + hb + hl] = sA[r][hl];
            g_adst[grow * 8 + hb + hl] = sD[r][hl];
        }
    }
}

// ---------------- CSR build ----------------
__global__ void k_hist(const void* __restrict__ ei, int e) {
    int t = blockIdx.x * blockDim.x + threadIdx.x;
    int is64 = g_is64;
    int base = 2 * t;
    if (base + 1 < e) {
        int d0, d1;
        if (is64) {
            longlong2 v = ((const longlong2*)ei)[(e >> 1) + t];
            d0 = (int)v.x; d1 = (int)v.y;
        } else {
            int2 v = ((const int2*)ei)[(e >> 1) + t];
            d0 = v.x; d1 = v.y;
        }
        atomicAdd(&g_deg[d0], 1);
        atomicAdd(&g_deg[d1], 1);
    } else if (base < e) {
        int d = load_idx(ei, e + base, is64);
        atomicAdd(&g_deg[d], 1);
    }
}

// ---------------- scanA: block-local scan (+ cursor zeroing) ----------------
__global__ void k_scanA(int n) {
    int i = blockIdx.x * 256 + threadIdx.x;
    int lane = threadIdx.x & 31, wid = threadIdx.x >> 5;
    if (i < n) g_cursor[i] = 0;
    int v = (i < n) ? (g_deg[i] + 1) : 0;
    int x = v;
    #pragma unroll
    for (int o = 1; o < 32; o <<= 1) {
        int y = __shfl_up_sync(0xffffffffu, x, o);
        if (lane >= o) x += y;
    }
    __shared__ int ws[8];
    if (lane == 31) ws[wid] = x;
    __syncthreads();
    if (threadIdx.x < 8) {
        int w = ws[threadIdx.x];
        #pragma unroll
        for (int o = 1; o < 8; o <<= 1) {
            int y = __shfl_up_sync(0xffu, w, o);
            if ((int)threadIdx.x >= o) w += y;
        }
        ws[threadIdx.x] = w;
    }
    __syncthreads();
    int base = (wid ? ws[wid - 1] : 0);
    if (i < n) g_rowstart[i] = base + x - v;
    if (threadIdx.x == 255) g_bsum[blockIdx.x] = ws[7];
}

// ---------------- scanCB: each block computes its own offset, applies it ----------------
__global__ void k_scanCB(int n, int total, int nb) {
    int b = blockIdx.x;
    int t = threadIdx.x;
    int lane = t & 31, wid = t >> 5;
    int v = (t < b && t < nb) ? g_bsum[t] : 0;
    #pragma unroll
    for (int o = 16; o; o >>= 1) v += __shfl_xor_sync(0xffffffffu, v, o);
    __shared__ int ws[8];
    __shared__ int sboff;
    if (lane == 0) ws[wid] = v;
    __syncthreads();
    if (t == 0) {
        int s = 0;
        #pragma unroll
        for (int k = 0; k < 8; k++) s += ws[k];
        sboff = s;
    }
    __syncthreads();
    int boff = sboff;
    int i = b * 256 + t;
    if (i < n) g_rowstart[i] += boff;
    if (i == 0) g_rowstart[n] = total;
}

__global__ void k_scatter(const void* __restrict__ ei, int e, int n) {
    int t = blockIdx.x * blockDim.x + threadIdx.x;
    int ep = e >> 1;
    int is64 = g_is64;
    if (t < ep) {
        int s0, s1, d0, d1;
        if (is64) {
            longlong2 vs = ((const longlong2*)ei)[t];
            longlong2 vd = ((const longlong2*)ei)[ep + t];
            s0 = (int)vs.x; s1 = (int)vs.y; d0 = (int)vd.x; d1 = (int)vd.y;
        } else {
            int2 vs = ((const int2*)ei)[t];
            int2 vd = ((const int2*)ei)[ep + t];
            s0 = vs.x; s1 = vs.y; d0 = vd.x; d1 = vd.y;
        }
        int p0 = atomicAdd(&g_cursor[d0], 1);
        g_csr[g_rowstart[d0] + p0] = s0;
        int p1 = atomicAdd(&g_cursor[d1], 1);
        g_csr[g_rowstart[d1] + p1] = s1;
    } else if ((e & 1) && t == ep) {
        int src = load_idx(ei, e - 1, is64);
        int dst = load_idx(ei, 2 * e - 1, is64);
        int p = atomicAdd(&g_cursor[dst], 1);
        g_csr[g_rowstart[dst] + p] = src;
    } else {
        int node = t - ep - (e & 1);
        if (node < n) {
            int p = atomicAdd(&g_cursor[node], 1);
            g_csr[g_rowstart[node] + p] = node;
        }
    }
}

// ---------------- layer-1 aggregation + fused layer-2 projection ----------------
// Main loop: lane L owns (edge L>>3, head L&7) for softmax -> 1 exp/lane,
// 1 asrc load/lane. Per-head sums kept per-lane, folded with shfl_xor(8,16).
__global__ void k_agg1(const float* __restrict__ b1, const float* __restrict__ W2,
                       const float* __restrict__ as2w, const float* __restrict__ ad2w, int n) {
    int w    = (blockIdx.x * blockDim.x + threadIdx.x) >> 5;
    int lane = threadIdx.x & 31;
    if (w >= n) return;
    int row = g_rowstart[w], end = g_rowstart[w + 1];
    int hsel  = lane >> 2;               // head for the fma broadcast
    int hlane = lane & 7;                // head this lane owns in softmax
    float adlf = g_adst[w * 8 + hlane];  // all 32 lanes (4x replicated)

    float s_part = 0.f;                  // per-lane partial of s[hlane]
    float2 acc[4] = {{0.f,0.f},{0.f,0.f},{0.f,0.f},{0.f,0.f}};

    int j = row;
    for (; j + 3 < end; j += 4) {
        int n0 = g_csr[j], n1 = g_csr[j + 1], n2 = g_csr[j + 2], n3 = g_csr[j + 3];
        float4 v0 = *(const float4*)(g_xph + (size_t)n0 * 256 + lane * 8);
        float4 v1 = *(const float4*)(g_xph + (size_t)n1 * 256 + lane * 8);
        float4 v2 = *(const float4*)(g_xph + (size_t)n2 * 256 + lane * 8);
        float4 v3 = *(const float4*)(g_xph + (size_t)n3 * 256 + lane * 8);
        // softmax: lane owns (edge lane>>3, head lane&7)
        int eidx = lane >> 3;
        int myn = n0;
        if (eidx == 1) myn = n1;
        else if (eidx == 2) myn = n2;
        else if (eidx == 3) myn = n3;
        float ev = g_asrc[myn * 8 + hlane] + adlf;
        ev = fmaxf(ev, 0.2f * ev);
        float p = __expf(ev);
        s_part += p;
        // broadcast p of (edge i, head hsel) from lane 8*i + hsel
        float q0 = __shfl_sync(0xffffffffu, p, hsel);
        float q1 = __shfl_sync(0xffffffffu, p, 8 + hsel);
        float q2 = __shfl_sync(0xffffffffu, p, 16 + hsel);
        float q3 = __shfl_sync(0xffffffffu, p, 24 + hsel);
        const __half2* h0 = (const __half2*)&v0;
        const __half2* h1 = (const __half2*)&v1;
        const __half2* h2 = (const __half2*)&v2;
        const __half2* h3 = (const __half2*)&v3;
        #pragma unroll
        for (int k = 0; k < 4; k++) {
            float2 f0 = __half22float2(h0[k]);
            float2 f1 = __half22float2(h1[k]);
            float2 f2 = __half22float2(h2[k]);
            float2 f3 = __half22float2(h3[k]);
            acc[k].x = fmaf(f0.x, q0, fmaf(f1.x, q1, fmaf(f2.x, q2, fmaf(f3.x, q3, acc[k].x))));
            acc[k].y = fmaf(f0.y, q0, fmaf(f1.y, q1, fmaf(f2.y, q2, fmaf(f3.y, q3, acc[k].y))));
        }
    }
    for (; j < end; j++) {
        int n0 = g_csr[j];
        float4 v0 = *(const float4*)(g_xph + (size_t)n0 * 256 + lane * 8);
        float p = 0.f;
        if (lane < 8) {
            float ev = g_asrc[n0 * 8 + lane] + adlf;   // lane<8 => hlane==lane
            ev = fmaxf(ev, 0.2f * ev);
            p = __expf(ev);
            s_part += p;                                // counted once (lanes 0-7)
        }
        float q0 = __shfl_sync(0xffffffffu, p, hsel);
        const __half2* h0 = (const __half2*)&v0;
        #pragma unroll
        for (int k = 0; k < 4; k++) {
            float2 f0 = __half22float2(h0[k]);
            acc[k].x = fmaf(f0.x, q0, acc[k].x);
            acc[k].y = fmaf(f0.y, q0, acc[k].y);
        }
    }

    // fold per-lane partials into per-head sums: lanes with equal (lane&7)
    s_part += __shfl_xor_sync(0xffffffffu, s_part, 8);
    s_part += __shfl_xor_sync(0xffffffffu, s_part, 16);
    float sh = __shfl_sync(0xffffffffu, s_part, hsel);   // lane hsel holds head hsel
    float inv = 1.f / sh;

    float4 b4a = *(const float4*)(b1 + 8 * lane);
    float4 b4b = *(const float4*)(b1 + 8 * lane + 4);
    float hch[8];
    hch[0] = fmaxf(acc[0].x * inv + b4a.x, 0.f);
    hch[1] = fmaxf(acc[0].y * inv + b4a.y, 0.f);
    hch[2] = fmaxf(acc[1].x * inv + b4a.z, 0.f);
    hch[3] = fmaxf(acc[1].y * inv + b4a.w, 0.f);
    hch[4] = fmaxf(acc[2].x * inv + b4b.x, 0.f);
    hch[5] = fmaxf(acc[2].y * inv + b4b.y, 0.f);
    hch[6] = fmaxf(acc[3].x * inv + b4b.z, 0.f);
    hch[7] = fmaxf(acc[3].y * inv + b4b.w, 0.f);
    float o0 = 0.f, o1 = 0.f;
    #pragma unroll
    for (int q = 0; q < 4; q++) {
        float4 w4 = *(const float4*)(W2 + 16 * lane + 4 * q);
        o0 += hch[2 * q] * w4.x + hch[2 * q + 1] * w4.z;
        o1 += hch[2 * q] * w4.y + hch[2 * q + 1] * w4.w;
    }
    #pragma unroll
    for (int off = 16; off; off >>= 1) {
        o0 += __shfl_xor_sync(0xffffffffu, o0, off);
        o1 += __shfl_xor_sync(0xffffffffu, o1, off);
    }
    if (lane == 0) {
        g_hp[w * 2 + 0] = o0;
        g_hp[w * 2 + 1] = o1;
        g_as2[w] = o0 * as2w[0] + o1 * as2w[1];
        g_ad2[w] = o0 * ad2w[0] + o1 * ad2w[1];
    }
}

// ---------------- layer-2 aggregation ----------------
__global__ void k_agg2(const float* __restrict__ b2, float* __restrict__ out, int n) {
    int w    = (blockIdx.x * blockDim.x + threadIdx.x) >> 5;
    int lane = threadIdx.x & 31;
    if (w >= n) return;
    int row = g_rowstart[w], end = g_rowstart[w + 1];
    float adn = g_ad2[w];

    float s = 0.f, a0 = 0.f, a1 = 0.f;
    for (int j = row + lane; j < end; j += 32) {
        int src = g_csr[j];
        float e = g_as2[src] + adn;
        e = fmaxf(e, 0.2f * e);
        float p = __expf(e);
        float2 hp = *(const float2*)(g_hp + 2 * src);
        s  += p;
        a0 = fmaf(hp.x, p, a0);
        a1 = fmaf(hp.y, p, a1);
    }
    #pragma unroll
    for (int off = 16; off; off >>= 1) {
        s  += __shfl_xor_sync(0xffffffffu, s,  off);
        a0 += __shfl_xor_sync(0xffffffffu, a0, off);
        a1 += __shfl_xor_sync(0xffffffffu, a1, off);
    }
    if (lane == 0) {
        out[w * 2 + 0] = a0 / s + b2[0];
        out[w * 2 + 1] = a1 / s + b2[1];
    }
}

// ---------------- launch (R14 topology) ----------------
extern "C" void kernel_launch(void* const* d_in, const int* in_sizes, int n_in,
                              void* d_out, int out_size) {
    const float* x   = (const float*)d_in[0];
    const void*  ei  = d_in[1];
    const float* W1  = (const float*)d_in[2];
    const float* as1 = (const float*)d_in[3];
    const float* ad1 = (const float*)d_in[4];
    const float* b1  = (const float*)d_in[5];
    const float* W2  = (const float*)d_in[6];
    const float* as2 = (const float*)d_in[7];
    const float* ad2 = (const float*)d_in[8];
    const float* b2  = (const float*)d_in[9];

    int n = in_sizes[0] / 256;
    int e = in_sizes[1] / 2;

    int warpBlocks = (n * 32 + 255) / 256;
    int nb = (n + 255) / 256;

    static cudaStream_t s1 = 0, s2 = 0;
    static cudaEvent_t ev0 = 0, ev1 = 0, ev2 = 0;
    if (!s1) {
        cudaStreamCreateWithFlags(&s1, cudaStreamNonBlocking);
        cudaStreamCreateWithFlags(&s2, cudaStreamNonBlocking);
        cudaEventCreateWithFlags(&ev0, cudaEventDisableTiming);
        cudaEventCreateWithFlags(&ev1, cudaEventDisableTiming);
        cudaEventCreateWithFlags(&ev2, cudaEventDisableTiming);
    }

    cudaEventRecord(ev0, 0);
    cudaStreamWaitEvent(s1, ev0, 0);
    cudaStreamWaitEvent(s2, ev0, 0);

    // branch A: GEMM + fused logits
    dim3 gg((n + 127) / 128, 2);
    k_gemm1<<<gg, 256, 0, s1>>>(x, W1, as1, ad1, n);

    // branch B: CSR build (5 nodes)
    k_init<<<(n + 255) / 256, 256, 0, s2>>>((const int*)ei, n);
    k_hist<<<((e >> 1) + 256) / 256, 256, 0, s2>>>(ei, e);
    k_scanA<<<nb, 256, 0, s2>>>(n);
    k_scanCB<<<nb, 256, 0, s2>>>(n, e + n, nb);
    int scatterThreads = (e >> 1) + (e & 1) + n;
    k_scatter<<<(scatterThreads + 255) / 256, 256, 0, s2>>>(ei, e, n);

    // join onto s1, run aggs there
    cudaEventRecord(ev2, s2);
    cudaStreamWaitEvent(s1, ev2, 0);

    k_agg1<<<warpBlocks, 256, 0, s1>>>(b1, W2, as2, ad2, n);
    k_agg2<<<warpBlocks, 256, 0, s1>>>(b2, (float*)d_out, n);

    cudaEventRecord(ev1, s1);
    cudaStreamWaitEvent(0, ev1, 0);
}

// round 16
// speedup vs baseline: 1.0002x; 1.0002x over previous
#include <cuda_runtime.h>
#include <cuda_fp16.h>
#include <math.h>
#include <stdint.h>

#define NMAX 50000
#define EMAX 800000
#define TOT_E (EMAX + NMAX)

// ---------------- scratch ----------------
// g_deg: zero at static init; k_scanA writes 0 back after reading, so every
// replay starts with the all-zero invariant intact.
__device__ __half g_xph[NMAX * 256];
__device__ float  g_asrc[NMAX * 8];
__device__ float  g_adst[NMAX * 8];
__device__ int    g_deg[NMAX];
__device__ int    g_rowstart[NMAX + 1];
__device__ int    g_cursor[NMAX];
__device__ int    g_csr[TOT_E];
__device__ float4 g_nd[NMAX];           // {hp0, hp1, as2, ad2} per node
__device__ int    g_is64;
__device__ int    g_bsum[256];

// ---------------- mma helpers ----------------
__device__ __forceinline__ uint32_t sptr(const void* p) {
    return (uint32_t)__cvta_generic_to_shared(p);
}
__device__ __forceinline__ void ldsm4(uint32_t* r, uint32_t a) {
    asm volatile("ldmatrix.sync.aligned.m8n8.x4.shared.b16 {%0,%1,%2,%3},[%4];"
        : "=r"(r[0]), "=r"(r[1]), "=r"(r[2]), "=r"(r[3]) : "r"(a));
}
__device__ __forceinline__ void ldsm4t(uint32_t* r, uint32_t a) {
    asm volatile("ldmatrix.sync.aligned.m8n8.x4.trans.shared.b16 {%0,%1,%2,%3},[%4];"
        : "=r"(r[0]), "=r"(r[1]), "=r"(r[2]), "=r"(r[3]) : "r"(a));
}
__device__ __forceinline__ void mma16816(float* c, const uint32_t* a, uint32_t b0, uint32_t b1) {
    asm volatile(
        "mma.sync.aligned.m16n8k16.row.col.f32.f16.f16.f32 "
        "{%0,%1,%2,%3},{%4,%5,%6,%7},{%8,%9},{%0,%1,%2,%3};"
        : "+f"(c[0]), "+f"(c[1]), "+f"(c[2]), "+f"(c[3])
        : "r"(a[0]), "r"(a[1]), "r"(a[2]), "r"(a[3]), "r"(b0), "r"(b1));
}

__device__ __forceinline__ int load_idx(const void* ei, int i, int is64) {
    if (is64) return (int)((const long long*)ei)[i];
    return ((const int*)ei)[i];
}

// ---------------- dtype detect only (deg self-zeroes in scanA) ----------------
__global__ void k_detect(const int* __restrict__ ei32) {
    if (threadIdx.x < 32) {
        int bad = 0;
        #pragma unroll
        for (int i = threadIdx.x; i < 64; i += 32)
            bad |= (ei32[2 * i + 1] != 0);
        unsigned m = __ballot_sync(0xffffffffu, bad);
        if (threadIdx.x == 0) g_is64 = (m == 0);
    }
}

// ---------------- layer-1 GEMM + fused attention logits (double-buffered) ----------------
__global__ void __launch_bounds__(256, 2) k_gemm1(const float* __restrict__ X,
                                                  const float* __restrict__ W,
                                                  const float* __restrict__ As1,
                                                  const float* __restrict__ Ad1, int M) {
    const int BM = 128;
    __shared__ __half As[2][BM][40];
    __shared__ __half Bs[2][32][136];
    __shared__ float  sA[128][4];
    __shared__ float  sD[128][4];
    int t    = threadIdx.x;
    int wid  = t >> 5, lane = t & 31;
    int lr   = lane & 7, lg = lane >> 3;
    int wm   = (wid >> 1) * 32;
    int wn   = (wid & 1) * 64;
    int rowBase = blockIdx.x * BM;
    int colBase = blockIdx.y * BM;
    int hb      = blockIdx.y * 4;

    #pragma unroll
    for (int i = t; i < 512; i += 256) {
        ((float*)sA)[i] = 0.f;
        ((float*)sD)[i] = 0.f;
    }

    float c[2][8][4];
    #pragma unroll
    for (int i = 0; i < 2; i++)
        #pragma unroll
        for (int j = 0; j < 8; j++)
            #pragma unroll
            for (int k = 0; k < 4; k++) c[i][j][k] = 0.f;

    int ar[4], ak[4], br[4], bc[4];
    #pragma unroll
    for (int i = 0; i < 4; i++) {
        int q = t + i * 256;
        ar[i] = q >> 3; ak[i] = (q & 7) * 4;
        br[i] = q >> 5; bc[i] = (q & 31) * 4;
    }

    float4 ra[4], rb[4];
    #pragma unroll
    for (int i = 0; i < 4; i++) {
        int grow = rowBase + ar[i];
        ra[i] = (grow < M) ? *(const float4*)(X + (size_t)grow * 256 + ak[i])
                           : make_float4(0.f, 0.f, 0.f, 0.f);
        rb[i] = *(const float4*)(W + (size_t)br[i] * 256 + colBase + bc[i]);
    }
    #pragma unroll
    for (int i = 0; i < 4; i++) {
        *(__half2*)&As[0][ar[i]][ak[i]]     = __floats2half2_rn(ra[i].x, ra[i].y);
        *(__half2*)&As[0][ar[i]][ak[i] + 2] = __floats2half2_rn(ra[i].z, ra[i].w);
        *(__half2*)&Bs[0][br[i]][bc[i]]     = __floats2half2_rn(rb[i].x, rb[i].y);
        *(__half2*)&Bs[0][br[i]][bc[i] + 2] = __floats2half2_rn(rb[i].z, rb[i].w);
    }
    __syncthreads();

    int cur = 0;
    for (int kt = 0; kt < 256; kt += 32) {
        bool more = (kt + 32) < 256;
        if (more) {
            #pragma unroll
            for (int i = 0; i < 4; i++) {
                int grow = rowBase + ar[i];
                ra[i] = (grow < M) ? *(const float4*)(X + (size_t)grow * 256 + kt + 32 + ak[i])
                                   : make_float4(0.f, 0.f, 0.f, 0.f);
                rb[i] = *(const float4*)(W + (size_t)(kt + 32 + br[i]) * 256 + colBase + bc[i]);
            }
        }
        #pragma unroll
        for (int ks = 0; ks < 2; ks++) {
            uint32_t a[2][4], b[4][4];
            #pragma unroll
            for (int mt = 0; mt < 2; mt++) {
                int row = wm + mt * 16 + lr + (lg & 1) * 8;
                int col = ks * 16 + (lg >> 1) * 8;
                ldsm4(a[mt], sptr(&As[cur][row][col]));
            }
            #pragma unroll
            for (int ng = 0; ng < 4; ng++) {
                int krow = ks * 16 + lr + (lg & 1) * 8;
                int col  = wn + ng * 16 + (lg >> 1) * 8;
                ldsm4t(b[ng], sptr(&Bs[cur][krow][col]));
            }
            #pragma unroll
            for (int mt = 0; mt < 2; mt++)
                #pragma unroll
                for (int nt = 0; nt < 8; nt++)
                    mma16816(c[mt][nt], a[mt], b[nt >> 1][(nt & 1) * 2],
                             b[nt >> 1][(nt & 1) * 2 + 1]);
        }
        if (more) {
            int nxt = cur ^ 1;
            #pragma unroll
            for (int i = 0; i < 4; i++) {
                *(__half2*)&As[nxt][ar[i]][ak[i]]     = __floats2half2_rn(ra[i].x, ra[i].y);
                *(__half2*)&As[nxt][ar[i]][ak[i] + 2] = __floats2half2_rn(ra[i].z, ra[i].w);
                *(__half2*)&Bs[nxt][br[i]][bc[i]]     = __floats2half2_rn(rb[i].x, rb[i].y);
                *(__half2*)&Bs[nxt][br[i]][bc[i] + 2] = __floats2half2_rn(rb[i].z, rb[i].w);
            }
            __syncthreads();
            cur = nxt;
        }
    }

    // epilogue 1: store xp fp16
    #pragma unroll
    for (int mt = 0; mt < 2; mt++) {
        int r0 = rowBase + wm + mt * 16 + (lane >> 2);
        #pragma unroll
        for (int nt = 0; nt < 8; nt++) {
            int col = colBase + wn + nt * 8 + (lane & 3) * 2;
            if (r0 < M)
                *(__half2*)(g_xph + (size_t)r0 * 256 + col) =
                    __floats2half2_rn(c[mt][nt][0], c[mt][nt][1]);
            if (r0 + 8 < M)
                *(__half2*)(g_xph + (size_t)(r0 + 8) * 256 + col) =
                    __floats2half2_rn(c[mt][nt][2], c[mt][nt][3]);
        }
    }

    // epilogue 2: attention logit partials
    float asw[16], adw[16];
    #pragma unroll
    for (int nt = 0; nt < 8; nt++)
        #pragma unroll
        for (int b = 0; b < 2; b++) {
            int col = wn + nt * 8 + (lane & 3) * 2 + b;
            asw[nt * 2 + b] = As1[colBase + col];
            adw[nt * 2 + b] = Ad1[colBase + col];
        }
    int h0 = wn >> 5, h1 = h0 + 1;
    #pragma unroll
    for (int mt = 0; mt < 2; mt++)
        #pragma unroll
        for (int hf = 0; hf < 2; hf++) {
            int rl = wm + mt * 16 + (lane >> 2) + 8 * hf;
            float s0 = 0.f, s1 = 0.f, d0 = 0.f, d1 = 0.f;
            #pragma unroll
            for (int nt = 0; nt < 8; nt++) {
                float v0 = c[mt][nt][hf * 2 + 0];
                float v1 = c[mt][nt][hf * 2 + 1];
                float cs = v0 * asw[nt * 2] + v1 * asw[nt * 2 + 1];
                float cd = v0 * adw[nt * 2] + v1 * adw[nt * 2 + 1];
                if (nt < 4) { s0 += cs; d0 += cd; }
                else        { s1 += cs; d1 += cd; }
            }
            atomicAdd(&sA[rl][h0], s0);
            atomicAdd(&sA[rl][h1], s1);
            atomicAdd(&sD[rl][h0], d0);
            atomicAdd(&sD[rl][h1], d1);
        }
    __syncthreads();
    #pragma unroll
    for (int i = t; i < 512; i += 256) {
        int r = i >> 2, hl = i & 3;
        int grow = rowBase + r;
        if (grow < M) {
            g_asrc[grow * 8 + hb + hl] = sA[r][hl];
            g_adst[grow * 8 + hb + hl] = sD[r][hl];
        }
    }
}

// ---------------- CSR build ----------------
__global__ void k_hist(const void* __restrict__ ei, int e) {
    int t = blockIdx.x * blockDim.x + threadIdx.x;
    int is64 = g_is64;
    int base = 2 * t;
    if (base + 1 < e) {
        int d0, d1;
        if (is64) {
            longlong2 v = ((const longlong2*)ei)[(e >> 1) + t];
            d0 = (int)v.x; d1 = (int)v.y;
        } else {
            int2 v = ((const int2*)ei)[(e >> 1) + t];
            d0 = v.x; d1 = v.y;
        }
        atomicAdd(&g_deg[d0], 1);
        atomicAdd(&g_deg[d1], 1);
    } else if (base < e) {
        int d = load_idx(ei, e + base, is64);
        atomicAdd(&g_deg[d], 1);
    }
}

// ---------------- scanA: block-local scan; zeroes cursor AND deg (self-reset) ----------
__global__ void k_scanA(int n) {
    int i = blockIdx.x * 256 + threadIdx.x;
    int lane = threadIdx.x & 31, wid = threadIdx.x >> 5;
    int v = 0;
    if (i < n) {
        g_cursor[i] = 0;
        v = g_deg[i] + 1;
        g_deg[i] = 0;            // restore invariant for the next replay
    }
    int x = v;
    #pragma unroll
    for (int o = 1; o < 32; o <<= 1) {
        int y = __shfl_up_sync(0xffffffffu, x, o);
        if (lane >= o) x += y;
    }
    __shared__ int ws[8];
    if (lane == 31) ws[wid] = x;
    __syncthreads();
    if (threadIdx.x < 8) {
        int w = ws[threadIdx.x];
        #pragma unroll
        for (int o = 1; o < 8; o <<= 1) {
            int y = __shfl_up_sync(0xffu, w, o);
            if ((int)threadIdx.x >= o) w += y;
        }
        ws[threadIdx.x] = w;
    }
    __syncthreads();
    int base = (wid ? ws[wid - 1] : 0);
    if (i < n) g_rowstart[i] = base + x - v;
    if (threadIdx.x == 255) g_bsum[blockIdx.x] = ws[7];
}

// ---------------- scanCB: each block computes its own offset, applies it ----------------
__global__ void k_scanCB(int n, int total, int nb) {
    int b = blockIdx.x;
    int t = threadIdx.x;
    int lane = t & 31, wid = t >> 5;
    int v = (t < b && t < nb) ? g_bsum[t] : 0;
    #pragma unroll
    for (int o = 16; o; o >>= 1) v += __shfl_xor_sync(0xffffffffu, v, o);
    __shared__ int ws[8];
    __shared__ int sboff;
    if (lane == 0) ws[wid] = v;
    __syncthreads();
    if (t == 0) {
        int s = 0;
        #pragma unroll
        for (int k = 0; k < 8; k++) s += ws[k];
        sboff = s;
    }
    __syncthreads();
    int boff = sboff;
    int i = b * 256 + t;
    if (i < n) g_rowstart[i] += boff;
    if (i == 0) g_rowstart[n] = total;
}

__global__ void k_scatter(const void* __restrict__ ei, int e, int n) {
    int t = blockIdx.x * blockDim.x + threadIdx.x;
    int ep = e >> 1;
    int is64 = g_is64;
    if (t < ep) {
        int s0, s1, d0, d1;
        if (is64) {
            longlong2 vs = ((const longlong2*)ei)[t];
            longlong2 vd = ((const longlong2*)ei)[ep + t];
            s0 = (int)vs.x; s1 = (int)vs.y; d0 = (int)vd.x; d1 = (int)vd.y;
        } else {
            int2 vs = ((const int2*)ei)[t];
            int2 vd = ((const int2*)ei)[ep + t];
            s0 = vs.x; s1 = vs.y; d0 = vd.x; d1 = vd.y;
        }
        int p0 = atomicAdd(&g_cursor[d0], 1);
        g_csr[g_rowstart[d0] + p0] = s0;
        int p1 = atomicAdd(&g_cursor[d1], 1);
        g_csr[g_rowstart[d1] + p1] = s1;
    } else if ((e & 1) && t == ep) {
        int src = load_idx(ei, e - 1, is64);
        int dst = load_idx(ei, 2 * e - 1, is64);
        int p = atomicAdd(&g_cursor[dst], 1);
        g_csr[g_rowstart[dst] + p] = src;
    } else {
        int node = t - ep - (e & 1);
        if (node < n) {
            int p = atomicAdd(&g_cursor[node], 1);
            g_csr[g_rowstart[node] + p] = node;
        }
    }
}

// ---------------- layer-1 aggregation + fused layer-2 projection ----------------
__global__ void k_agg1(const float* __restrict__ b1, const float* __restrict__ W2,
                       const float* __restrict__ as2w, const float* __restrict__ ad2w, int n) {
    int w    = (blockIdx.x * blockDim.x + threadIdx.x) >> 5;
    int lane = threadIdx.x & 31;
    if (w >= n) return;
    int row = g_rowstart[w], end = g_rowstart[w + 1];
    int hsel  = lane >> 2;
    int hlane = lane & 7;
    float adlf = g_adst[w * 8 + hlane];

    float s_part = 0.f;
    float2 acc[4] = {{0.f,0.f},{0.f,0.f},{0.f,0.f},{0.f,0.f}};

    int j = row;
    for (; j + 3 < end; j += 4) {
        int n0 = g_csr[j], n1 = g_csr[j + 1], n2 = g_csr[j + 2], n3 = g_csr[j + 3];
        float4 v0 = *(const float4*)(g_xph + (size_t)n0 * 256 + lane * 8);
        float4 v1 = *(const float4*)(g_xph + (size_t)n1 * 256 + lane * 8);
        float4 v2 = *(const float4*)(g_xph + (size_t)n2 * 256 + lane * 8);
        float4 v3 = *(const float4*)(g_xph + (size_t)n3 * 256 + lane * 8);
        int eidx = lane >> 3;
        int myn = n0;
        if (eidx == 1) myn = n1;
        else if (eidx == 2) myn = n2;
        else if (eidx == 3) myn = n3;
        float ev = g_asrc[myn * 8 + hlane] + adlf;
        ev = fmaxf(ev, 0.2f * ev);
        float p = __expf(ev);
        s_part += p;
        float q0 = __shfl_sync(0xffffffffu, p, hsel);
        float q1 = __shfl_sync(0xffffffffu, p, 8 + hsel);
        float q2 = __shfl_sync(0xffffffffu, p, 16 + hsel);
        float q3 = __shfl_sync(0xffffffffu, p, 24 + hsel);
        const __half2* h0 = (const __half2*)&v0;
        const __half2* h1 = (const __half2*)&v1;
        const __half2* h2 = (const __half2*)&v2;
        const __half2* h3 = (const __half2*)&v3;
        #pragma unroll
        for (int k = 0; k < 4; k++) {
            float2 f0 = __half22float2(h0[k]);
            float2 f1 = __half22float2(h1[k]);
            float2 f2 = __half22float2(h2[k]);
            float2 f3 = __half22float2(h3[k]);
            acc[k].x = fmaf(f0.x, q0, fmaf(f1.x, q1, fmaf(f2.x, q2, fmaf(f3.x, q3, acc[k].x))));
            acc[k].y = fmaf(f0.y, q0, fmaf(f1.y, q1, fmaf(f2.y, q2, fmaf(f3.y, q3, acc[k].y))));
        }
    }
    for (; j < end; j++) {
        int n0 = g_csr[j];
        float4 v0 = *(const float4*)(g_xph + (size_t)n0 * 256 + lane * 8);
        float p = 0.f;
        if (lane < 8) {
            float ev = g_asrc[n0 * 8 + lane] + adlf;
            ev = fmaxf(ev, 0.2f * ev);
            p = __expf(ev);
            s_part += p;
        }
        float q0 = __shfl_sync(0xffffffffu, p, hsel);
        const __half2* h0 = (const __half2*)&v0;
        #pragma unroll
        for (int k = 0; k < 4; k++) {
            float2 f0 = __half22float2(h0[k]);
            acc[k].x = fmaf(f0.x, q0, acc[k].x);
            acc[k].y = fmaf(f0.y, q0, acc[k].y);
        }
    }

    s_part += __shfl_xor_sync(0xffffffffu, s_part, 8);
    s_part += __shfl_xor_sync(0xffffffffu, s_part, 16);
    float sh = __shfl_sync(0xffffffffu, s_part, hsel);
    float inv = 1.f / sh;

    float4 b4a = *(const float4*)(b1 + 8 * lane);
    float4 b4b = *(const float4*)(b1 + 8 * lane + 4);
    float hch[8];
    hch[0] = fmaxf(acc[0].x * inv + b4a.x, 0.f);
    hch[1] = fmaxf(acc[0].y * inv + b4a.y, 0.f);
    hch[2] = fmaxf(acc[1].x * inv + b4a.z, 0.f);
    hch[3] = fmaxf(acc[1].y * inv + b4a.w, 0.f);
    hch[4] = fmaxf(acc[2].x * inv + b4b.x, 0.f);
    hch[5] = fmaxf(acc[2].y * inv + b4b.y, 0.f);
    hch[6] = fmaxf(acc[3].x * inv + b4b.z, 0.f);
    hch[7] = fmaxf(acc[3].y * inv + b4b.w, 0.f);
    float o0 = 0.f, o1 = 0.f;
    #pragma unroll
    for (int q = 0; q < 4; q++) {
        float4 w4 = *(const float4*)(W2 + 16 * lane + 4 * q);
        o0 += hch[2 * q] * w4.x + hch[2 * q + 1] * w4.z;
        o1 += hch[2 * q] * w4.y + hch[2 * q + 1] * w4.w;
    }
    #pragma unroll
    for (int off = 16; off; off >>= 1) {
        o0 += __shfl_xor_sync(0xffffffffu, o0, off);
        o1 += __shfl_xor_sync(0xffffffffu, o1, off);
    }
    if (lane == 0) {
        // packed node record: {hp0, hp1, as2, ad2}
        g_nd[w] = make_float4(o0, o1,
                              o0 * as2w[0] + o1 * as2w[1],
                              o0 * ad2w[0] + o1 * ad2w[1]);
    }
}

// ---------------- layer-2 aggregation (single LDG.128 per edge) ----------------
__global__ void k_agg2(const float* __restrict__ b2, float* __restrict__ out, int n) {
    int w    = (blockIdx.x * blockDim.x + threadIdx.x) >> 5;
    int lane = threadIdx.x & 31;
    if (w >= n) return;
    int row = g_rowstart[w], end = g_rowstart[w + 1];
    float adn = g_nd[w].w;

    float s = 0.f, a0 = 0.f, a1 = 0.f;
    for (int j = row + lane; j < end; j += 32) {
        int src = g_csr[j];
        float4 nd = g_nd[src];            // {hp0, hp1, as2, ad2}
        float e = nd.z + adn;
        e = fmaxf(e, 0.2f * e);
        float p = __expf(e);
        s  += p;
        a0 = fmaf(nd.x, p, a0);
        a1 = fmaf(nd.y, p, a1);
    }
    #pragma unroll
    for (int off = 16; off; off >>= 1) {
        s  += __shfl_xor_sync(0xffffffffu, s,  off);
        a0 += __shfl_xor_sync(0xffffffffu, a0, off);
        a1 += __shfl_xor_sync(0xffffffffu, a1, off);
    }
    if (lane == 0) {
        out[w * 2 + 0] = a0 / s + b2[0];
        out[w * 2 + 1] = a1 / s + b2[1];
    }
}

// ---------------- launch (R14 topology) ----------------
extern "C" void kernel_launch(void* const* d_in, const int* in_sizes, int n_in,
                              void* d_out, int out_size) {
    const float* x   = (const float*)d_in[0];
    const void*  ei  = d_in[1];
    const float* W1  = (const float*)d_in[2];
    const float* as1 = (const float*)d_in[3];
    const float* ad1 = (const float*)d_in[4];
    const float* b1  = (const float*)d_in[5];
    const float* W2  = (const float*)d_in[6];
    const float* as2 = (const float*)d_in[7];
    const float* ad2 = (const float*)d_in[8];
    const float* b2  = (const float*)d_in[9];

    int n = in_sizes[0] / 256;
    int e = in_sizes[1] / 2;

    int warpBlocks = (n * 32 + 255) / 256;
    int nb = (n + 255) / 256;

    static cudaStream_t s1 = 0, s2 = 0;
    static cudaEvent_t ev0 = 0, ev1 = 0, ev2 = 0;
    if (!s1) {
        cudaStreamCreateWithFlags(&s1, cudaStreamNonBlocking);
        cudaStreamCreateWithFlags(&s2, cudaStreamNonBlocking);
        cudaEventCreateWithFlags(&ev0, cudaEventDisableTiming);
        cudaEventCreateWithFlags(&ev1, cudaEventDisableTiming);
        cudaEventCreateWithFlags(&ev2, cudaEventDisableTiming);
    }

    cudaEventRecord(ev0, 0);
    cudaStreamWaitEvent(s1, ev0, 0);
    cudaStreamWaitEvent(s2, ev0, 0);

    // branch A: GEMM + fused logits
    dim3 gg((n + 127) / 128, 2);
    k_gemm1<<<gg, 256, 0, s1>>>(x, W1, as1, ad1, n);

    // branch B: CSR build (g_deg is all-zero: static init first call,
    // self-reset by the previous k_scanA on every replay)
    k_detect<<<1, 32, 0, s2>>>((const int*)ei);
    k_hist<<<((e >> 1) + 256) / 256, 256, 0, s2>>>(ei, e);
    k_scanA<<<nb, 256, 0, s2>>>(n);
    k_scanCB<<<nb, 256, 0, s2>>>(n, e + n, nb);
    int scatterThreads = (e >> 1) + (e & 1) + n;
    k_scatter<<<(scatterThreads + 255) / 256, 256, 0, s2>>>(ei, e, n);

    // join onto s1, run aggs there
    cudaEventRecord(ev2, s2);
    cudaStreamWaitEvent(s1, ev2, 0);

    k_agg1<<<warpBlocks, 256, 0, s1>>>(b1, W2, as2, ad2, n);
    k_agg2<<<warpBlocks, 256, 0, s1>>>(b2, (float*)d_out, n);

    cudaEventRecord(ev1, s1);
    cudaStreamWaitEvent(0, ev1, 0);
}